// round 2
// baseline (speedup 1.0000x reference)
#include <cuda_runtime.h>
#include <math.h>

// Problem constants (fixed by the reference)
#define S_LEN   1024
#define I_DIM   1024
#define H_DIM   2048
#define L_NUM   4

#define SCAN_CTAS     128
#define ROWS_PER_CTA  16              // H_DIM / SCAN_CTAS
#define SCAN_THREADS  128             // 4 warps, 4 rows per warp
#define SCAN_SMEM_BYTES (ROWS_PER_CTA * H_DIM * (int)sizeof(float))  // 131072 (weights only)

// Scratch (device globals — no allocation allowed)
__device__ float g_U [S_LEN * H_DIM];   // u_l(t) for current layer (8 MB)
__device__ float g_HA[S_LEN * H_DIM];   // hidden states of current layer (8 MB)
__device__ int   g_cnt[S_LEN];          // per-timestep arrival counters

// ---------------------------------------------------------------------------
// GEMM: C[M,N] = A[M,K] @ B[N,K]^T + bias1[n] + bias2[n]
// A row-major (K contiguous), B row-major (K contiguous) -> dual K-major tiles.
// 128x128 tile, BK=8, 256 threads, 8x8 per-thread microtile.
// ---------------------------------------------------------------------------
__global__ void gemm_bias_kernel(const float* __restrict__ A,
                                 const float* __restrict__ B,
                                 float* __restrict__ C,
                                 const float* __restrict__ bias1,
                                 const float* __restrict__ bias2,
                                 int M, int N, int K)
{
    __shared__ float As[8][128];
    __shared__ float Bs[8][128];

    const int tid = threadIdx.x;
    const int bm  = blockIdx.y * 128;
    const int bn  = blockIdx.x * 128;

    const int loadRow = tid >> 1;        // 0..127
    const int loadCol = (tid & 1) * 4;   // 0 or 4

    const int tx = tid & 15;             // n sub-tile
    const int ty = tid >> 4;             // m sub-tile

    float acc[8][8];
#pragma unroll
    for (int i = 0; i < 8; i++)
#pragma unroll
        for (int j = 0; j < 8; j++) acc[i][j] = 0.f;

    const float* Ag = A + (size_t)(bm + loadRow) * K + loadCol;
    const float* Bg = B + (size_t)(bn + loadRow) * K + loadCol;

    for (int k0 = 0; k0 < K; k0 += 8) {
        float4 av = *(const float4*)(Ag + k0);
        float4 bv = *(const float4*)(Bg + k0);
        As[loadCol + 0][loadRow] = av.x;
        As[loadCol + 1][loadRow] = av.y;
        As[loadCol + 2][loadRow] = av.z;
        As[loadCol + 3][loadRow] = av.w;
        Bs[loadCol + 0][loadRow] = bv.x;
        Bs[loadCol + 1][loadRow] = bv.y;
        Bs[loadCol + 2][loadRow] = bv.z;
        Bs[loadCol + 3][loadRow] = bv.w;
        __syncthreads();

#pragma unroll
        for (int k = 0; k < 8; k++) {
            float a[8], b[8];
#pragma unroll
            for (int i = 0; i < 8; i++) a[i] = As[k][ty * 8 + i];
#pragma unroll
            for (int j = 0; j < 8; j++) b[j] = Bs[k][tx * 8 + j];
#pragma unroll
            for (int i = 0; i < 8; i++)
#pragma unroll
                for (int j = 0; j < 8; j++)
                    acc[i][j] += a[i] * b[j];
        }
        __syncthreads();
    }

    // Epilogue with fused bias add, float4 stores
#pragma unroll
    for (int i = 0; i < 8; i++) {
        const int m = bm + ty * 8 + i;
        float* crow = C + (size_t)m * N + bn + tx * 8;
#pragma unroll
        for (int j = 0; j < 8; j += 4) {
            const int n = bn + tx * 8 + j;
            float4 v;
            v.x = acc[i][j + 0] + bias1[n + 0] + bias2[n + 0];
            v.y = acc[i][j + 1] + bias1[n + 1] + bias2[n + 1];
            v.z = acc[i][j + 2] + bias1[n + 2] + bias2[n + 2];
            v.w = acc[i][j + 3] + bias1[n + 3] + bias2[n + 3];
            *(float4*)(crow + j) = v;
        }
    }
}

// ---------------------------------------------------------------------------
// Persistent scan: h(t) = tanh(U[t] + Wh @ h(t-1)) over t = 0..S-1.
// Wh (H x H) lives sliced across 128 CTAs' SMEM (16 rows each).
// h(t-1) is read straight from L2 (__ldcg, pipelined) inside the FMA loop --
// its latency hides under the weight-LDS stream that owns the bottleneck.
// Cross-SM per-step handshake: release-fenced stores + atomicAdd on g_cnt[t];
// consumers poll a volatile counter, fence, then __ldcg the h vector.
// ---------------------------------------------------------------------------
__global__ void __launch_bounds__(SCAN_THREADS, 1)
scan_kernel(const float* __restrict__ Wh,    // layer's H x H row-major slice base
            const float* __restrict__ U,     // S x H (biases already folded in)
            float* __restrict__ Hout,        // S x H; reads t-1, writes t
            int* cnt,                        // [S] arrival counters
            int wait_target)                 // 128*(layer+1)
{
    extern __shared__ float smem[];
    float* sW = smem;                         // ROWS_PER_CTA * H_DIM floats

    const int tid  = threadIdx.x;
    const int lane = tid & 31;
    const int warp = tid >> 5;
    const int row0 = blockIdx.x * ROWS_PER_CTA;

    // Stage this CTA's 16 weight rows into SMEM (contiguous rows, coalesced)
    {
        const float4* Wg  = (const float4*)(Wh + (size_t)row0 * H_DIM);
        float4* sW4 = (float4*)sW;
        const int nvec = ROWS_PER_CTA * H_DIM / 4;
        for (int i = tid; i < nvec; i += SCAN_THREADS) sW4[i] = Wg[i];
    }
    __syncthreads();

    const float4* w0 = (const float4*)(sW + (warp * 4 + 0) * H_DIM);
    const float4* w1 = (const float4*)(sW + (warp * 4 + 1) * H_DIM);
    const float4* w2 = (const float4*)(sW + (warp * 4 + 2) * H_DIM);
    const float4* w3 = (const float4*)(sW + (warp * 4 + 3) * H_DIM);
    volatile int* vcnt = cnt;

    for (int t = 0; t < S_LEN; t++) {
        float a0 = 0.f, a1 = 0.f, a2 = 0.f, a3 = 0.f;

        if (t > 0) {
            if (tid == 0) {
                while (vcnt[t - 1] < wait_target) { }
                __threadfence();   // acquire side of the handshake
            }
            __syncthreads();

            // 4 rows per warp, h(t-1) streamed from L2 with one-deep prefetch
            const float4* hp4 = (const float4*)(Hout + (size_t)(t - 1) * H_DIM);
            float4 hv = __ldcg(hp4 + lane);
#pragma unroll
            for (int i = 0; i < H_DIM / 128; i++) {
                const int idx = lane + 32 * i;
                float4 hn;
                if (i + 1 < H_DIM / 128) hn = __ldcg(hp4 + idx + 32);
                float4 x0 = w0[idx];
                float4 x1 = w1[idx];
                float4 x2 = w2[idx];
                float4 x3 = w3[idx];
                a0 += x0.x * hv.x + x0.y * hv.y + x0.z * hv.z + x0.w * hv.w;
                a1 += x1.x * hv.x + x1.y * hv.y + x1.z * hv.z + x1.w * hv.w;
                a2 += x2.x * hv.x + x2.y * hv.y + x2.z * hv.z + x2.w * hv.w;
                a3 += x3.x * hv.x + x3.y * hv.y + x3.z * hv.z + x3.w * hv.w;
                hv = hn;
            }
#pragma unroll
            for (int off = 16; off > 0; off >>= 1) {
                a0 += __shfl_xor_sync(0xffffffffu, a0, off);
                a1 += __shfl_xor_sync(0xffffffffu, a1, off);
                a2 += __shfl_xor_sync(0xffffffffu, a2, off);
                a3 += __shfl_xor_sync(0xffffffffu, a3, off);
            }
        }

        // After xor-reduction every lane holds the full sums; lanes 0..3 commit
        if (lane < 4) {
            float accv = (lane == 0) ? a0 : (lane == 1) ? a1 : (lane == 2) ? a2 : a3;
            const int gr = row0 + warp * 4 + lane;
            const float v = tanhf(U[(size_t)t * H_DIM + gr] + accv);
            Hout[(size_t)t * H_DIM + gr] = v;
            __threadfence();   // release: order h-stores before the counter bump
        }
        __syncthreads();
        if (tid == 0) atomicAdd(cnt + t, 1);
    }
}

// ---------------------------------------------------------------------------
extern "C" void kernel_launch(void* const* d_in, const int* in_sizes, int n_in,
                              void* d_out, int out_size)
{
    const float* input = (const float*)d_in[0];   // (1, S, I)
    const float* Wi0   = (const float*)d_in[1];   // (H, I)
    const float* bi0   = (const float*)d_in[2];   // (H)
    const float* WiR   = (const float*)d_in[3];   // (L-1, H, H)
    const float* biR   = (const float*)d_in[4];   // (L-1, H)
    const float* Wh    = (const float*)d_in[5];   // (L, H, H)
    const float* bh    = (const float*)d_in[6];   // (L, H)
    float* out = (float*)d_out;                   // (S, 1, H) contiguous

    float *U, *HA; int* cnt;
    cudaGetSymbolAddress((void**)&U,  g_U);
    cudaGetSymbolAddress((void**)&HA, g_HA);
    cudaGetSymbolAddress((void**)&cnt, g_cnt);

    cudaFuncSetAttribute(scan_kernel,
                         cudaFuncAttributeMaxDynamicSharedMemorySize,
                         SCAN_SMEM_BYTES);

    // Counters must be zero at the start of every replay (graph-captured node)
    cudaMemsetAsync(cnt, 0, S_LEN * sizeof(int));

    dim3 gemm_grid(H_DIM / 128, S_LEN / 128);   // (16, 8)

    // Layer 0: U = X @ Wi0^T + bi0 + bh[0]; then scan with Wh[0]
    gemm_bias_kernel<<<gemm_grid, 256>>>(input, Wi0, U, bi0, bh, S_LEN, H_DIM, I_DIM);
    scan_kernel<<<SCAN_CTAS, SCAN_THREADS, SCAN_SMEM_BYTES>>>(Wh, U, HA, cnt, 128);

    // Layers 1..3
    for (int l = 1; l < L_NUM; l++) {
        const float* Wi_l = WiR + (size_t)(l - 1) * H_DIM * H_DIM;
        const float* bi_l = biR + (size_t)(l - 1) * H_DIM;
        const float* Wh_l = Wh  + (size_t)l * H_DIM * H_DIM;
        const float* bh_l = bh  + (size_t)l * H_DIM;
        float* dst = (l == L_NUM - 1) ? out : HA;

        gemm_bias_kernel<<<gemm_grid, 256>>>(HA, Wi_l, U, bi_l, bh_l,
                                             S_LEN, H_DIM, H_DIM);
        scan_kernel<<<SCAN_CTAS, SCAN_THREADS, SCAN_SMEM_BYTES>>>(Wh_l, U, dst,
                                                                  cnt, 128 * (l + 1));
    }
}